// round 7
// baseline (speedup 1.0000x reference)
#include <cuda_runtime.h>
#include <cstdint>

#define BS 32
#define LA 300
#define LB 1024
#define H  512
#define NROW (H*H)

// ---------------- scratch ----------------
__device__ float g_part[BS*16*H];
__device__ float g_bm[BS*H];          // b_mean [b][e]
__device__ float g_T[(long)BS*NROW];  // [b][k*H+d], values pre-rounded to tf32

// ---------------- helpers ----------------
__device__ __forceinline__ uint32_t f2tf(float f) {
    uint32_t r;
    asm("cvt.rna.tf32.f32 %0, %1;" : "=r"(r) : "f"(f));
    return r;
}
__device__ __forceinline__ void mma_tf32(float* c, uint32_t a0, uint32_t a1,
                                         uint32_t a2, uint32_t a3,
                                         uint32_t b0, uint32_t b1) {
    asm volatile("mma.sync.aligned.m16n8k8.row.col.f32.tf32.tf32.f32 "
                 "{%0,%1,%2,%3}, {%4,%5,%6,%7}, {%8,%9}, {%0,%1,%2,%3};"
                 : "+f"(c[0]), "+f"(c[1]), "+f"(c[2]), "+f"(c[3])
                 : "r"(a0), "r"(a1), "r"(a2), "r"(a3), "r"(b0), "r"(b1));
}

// ---------------- kernel 1: b_mean (row-major coalesced) ----------------
// grid (16,32), 128 thr: chunk of 64 rows, thread owns cols t*4..t*4+3
__global__ void k_bmean_part(const float* __restrict__ feat_b) {
    int chunk = blockIdx.x, b = blockIdx.y, t = threadIdx.x;
    const float4* p = (const float4*)(feat_b + ((long)b*LB + (long)chunk*64)*H) + t;
    float4 s = make_float4(0.f,0.f,0.f,0.f);
    #pragma unroll 8
    for (int j = 0; j < 64; j++) {
        float4 v = __ldg(p + (long)j*128);
        s.x += v.x; s.y += v.y; s.z += v.z; s.w += v.w;
    }
    *((float4*)(g_part + ((long)b*16 + chunk)*H) + t) = s;
}
__global__ void k_bmean_red() {
    long idx = (long)blockIdx.x*512 + threadIdx.x;
    long b = idx >> 9, d = idx & 511;
    float s = 0.f;
    #pragma unroll
    for (int c = 0; c < 16; c++) s += g_part[(b*16 + c)*H + d];
    g_bm[idx] = s * (1.0f/1024.0f);
}

// ---------------- kernel 2: T[b][r] = W2d x bm^T via mma.sync tf32 ----------------
// CTA 256 thr / 8 warps, 256 rows (32/warp, 2 slabs). K=512 in 32 chunks of 16.
#define SBM 528
#define SDW 260
#define WM_SMEM (32*SBM*4 + 32*SDW*4)   // 67584 + 33280 = 100864

__global__ void __launch_bounds__(256) k_wgemm_mma(const float* __restrict__ Wg) {
    extern __shared__ char smem[];
    uint32_t* sB = (uint32_t*)smem;             // [32][528] tf32 bits
    float* sD = (float*)(smem + 32*SBM*4);      // [32][260]

    int tid = threadIdx.x;
    int wid = tid >> 5, lane = tid & 31;
    int group = lane >> 2, tg = lane & 3;
    long r0 = (long)blockIdx.x * 256;
    int m0 = wid * 32;

    // stage bm (vectorized)
    for (int i = tid; i < 32*128; i += 256) {
        int n = i >> 7, k4 = i & 127;
        float4 v = __ldg((const float4*)g_bm + n*128 + k4);
        uint4 t;
        t.x = f2tf(v.x); t.y = f2tf(v.y); t.z = f2tf(v.z); t.w = f2tf(v.w);
        *(uint4*)(sB + n*SBM + k4*4) = t;
    }
    __syncthreads();

    const float4* A0 = (const float4*)(Wg + (long)(r0 + m0 + group)*H) + tg;
    const float4* A1 = A0 + 1024;      // +8 rows
    const float4* A2 = A0 + 2048;      // +16
    const float4* A3 = A0 + 3072;      // +24

    float acc[2][4][4];
    #pragma unroll
    for (int s = 0; s < 2; s++)
        #pragma unroll
        for (int i = 0; i < 4; i++)
            #pragma unroll
            for (int j = 0; j < 4; j++) acc[s][i][j] = 0.f;

    #pragma unroll 2
    for (int c = 0; c < 32; c++) {
        float4 w0 = __ldg(A0 + c*4);
        float4 w1 = __ldg(A1 + c*4);
        float4 w2 = __ldg(A2 + c*4);
        float4 w3 = __ldg(A3 + c*4);
        uint32_t ax0 = f2tf(w0.x), ax1 = f2tf(w1.x), ay0 = f2tf(w0.y), ay1 = f2tf(w1.y);
        uint32_t az0 = f2tf(w0.z), az1 = f2tf(w1.z), aw0 = f2tf(w0.w), aw1 = f2tf(w1.w);
        uint32_t bx0 = f2tf(w2.x), bx1 = f2tf(w3.x), by0 = f2tf(w2.y), by1 = f2tf(w3.y);
        uint32_t bz0 = f2tf(w2.z), bz1 = f2tf(w3.z), bw0 = f2tf(w2.w), bw1 = f2tf(w3.w);
        #pragma unroll
        for (int nt = 0; nt < 4; nt++) {
            uint4 bv = *(const uint4*)(sB + (nt*8 + group)*SBM + c*16 + tg*4);
            mma_tf32(acc[0][nt], ax0, ax1, ay0, ay1, bv.x, bv.y);
            mma_tf32(acc[0][nt], az0, az1, aw0, aw1, bv.z, bv.w);
            mma_tf32(acc[1][nt], bx0, bx1, by0, by1, bv.x, bv.y);
            mma_tf32(acc[1][nt], bz0, bz1, bw0, bw1, bv.z, bv.w);
        }
    }

    #pragma unroll
    for (int s = 0; s < 2; s++)
        #pragma unroll
        for (int nt = 0; nt < 4; nt++) {
            int n0 = nt*8 + tg*2;
            int rl = m0 + s*16 + group;
            sD[(n0  )*SDW + rl    ] = acc[s][nt][0];
            sD[(n0+1)*SDW + rl    ] = acc[s][nt][1];
            sD[(n0  )*SDW + rl + 8] = acc[s][nt][2];
            sD[(n0+1)*SDW + rl + 8] = acc[s][nt][3];
        }
    __syncthreads();
    #pragma unroll
    for (int n = 0; n < 32; n++) {
        uint32_t t = f2tf(sD[n*SDW + tid]);     // pre-round for gemm2 B
        g_T[(long)n*NROW + r0 + tid] = __uint_as_float(t);
    }
}

// ---------------- kernel 3: fused = feat_a @ T^T +bias +residual +LayerNorm ------
// CTA 512 thr / 16 warps (2 m-slabs x 8 n-slabs), tile 32 rows x 512 cols (full row),
// K = 32 chunks of 16, 4-stage cp.async. LN stats in-CTA.
#define G2_STG  34816                // A 2KB + B 32KB
#define G2_LNOFF (4*G2_STG)
#define G2_SMEM (G2_LNOFF + 256)

__global__ void __launch_bounds__(512) k_gemm2_ln(const float* __restrict__ A,
                                                  const float* __restrict__ bias,
                                                  const float* __restrict__ gamma,
                                                  const float* __restrict__ beta,
                                                  float* __restrict__ out) {
    extern __shared__ char smem[];
    float* ssum = (float*)(smem + G2_LNOFF);          // [32]
    float* ssq  = ssum + 32;                          // [32]
    int b = blockIdx.y, mt = blockIdx.x;
    int tid = threadIdx.x;
    int wid = tid >> 5, lane = tid & 31;
    int group = lane >> 2, tg = lane & 3;
    int wm = wid & 1, wc = wid >> 1;
    int row0 = mt * 32;
    const float* Ab = A + (long)b*LA*H;
    const float* Bb = g_T + (long)b*NROW;

    if (tid < 32) { ssum[tid] = 0.f; ssq[tid] = 0.f; }

    int rowA = tid >> 2, iA = tid & 3;                // A loader (tid<128)
    const float* srcA = Ab + (long)(row0 + rowA)*H + iA*4;
    int vszA = (tid < 128 && row0 + rowA < LA) ? 16 : 0;
    uint32_t dstA = (uint32_t)__cvta_generic_to_shared(smem) + rowA*64 + iA*16;

    auto issue = [&](int c) {
        uint32_t stg = (uint32_t)(c & 3) * G2_STG;
        if (tid < 128) {
            asm volatile("cp.async.cg.shared.global [%0], [%1], 16, %2;"
                         :: "r"(dstA + stg), "l"(srcA + c*16), "r"(vszA));
        }
        #pragma unroll
        for (int q = 0; q < 4; q++) {
            int g = q*512 + tid;
            int row = g >> 2, i = g & 3;
            const float* src = Bb + (long)row*H + c*16 + i*4;
            uint32_t dst = (uint32_t)__cvta_generic_to_shared(smem) + stg + 2048 + row*64 + i*16;
            asm volatile("cp.async.cg.shared.global [%0], [%1], 16;"
                         :: "r"(dst), "l"(src));
        }
        asm volatile("cp.async.commit_group;" ::: "memory");
    };

    issue(0); issue(1); issue(2);

    float acc[8][4];
    #pragma unroll
    for (int i = 0; i < 8; i++)
        #pragma unroll
        for (int j = 0; j < 4; j++) acc[i][j] = 0.f;

    for (int c = 0; c < 32; c++) {
        asm volatile("cp.async.wait_group 2;" ::: "memory");
        __syncthreads();
        if (c + 3 < 32) issue(c + 3);

        const char* st = smem + (c & 3)*G2_STG;
        const uint32_t* sA = (const uint32_t*)st;
        const uint32_t* sBt = (const uint32_t*)(st + 2048);

        uint4 a0v = *(const uint4*)(sA + (wm*16 + group)*16 + tg*4);
        uint4 a1v = *(const uint4*)(sA + (wm*16 + group + 8)*16 + tg*4);
        uint32_t ax0 = f2tf(__uint_as_float(a0v.x)), ax1 = f2tf(__uint_as_float(a1v.x));
        uint32_t ay0 = f2tf(__uint_as_float(a0v.y)), ay1 = f2tf(__uint_as_float(a1v.y));
        uint32_t az0 = f2tf(__uint_as_float(a0v.z)), az1 = f2tf(__uint_as_float(a1v.z));
        uint32_t aw0 = f2tf(__uint_as_float(a0v.w)), aw1 = f2tf(__uint_as_float(a1v.w));
        #pragma unroll
        for (int nt = 0; nt < 8; nt++) {
            uint4 bv = *(const uint4*)(sBt + (wc*64 + nt*8 + group)*16 + tg*4);
            mma_tf32(acc[nt], ax0, ax1, ay0, ay1, bv.x, bv.y);
            mma_tf32(acc[nt], az0, az1, aw0, aw1, bv.z, bv.w);
        }
        __syncthreads();
    }

    // epilogue: x = acc + bias + feat_a, then LN over the 512-wide row
    int rl0 = wm*16 + group;
    float s[2] = {0.f, 0.f}, q[2] = {0.f, 0.f};
    #pragma unroll
    for (int nt = 0; nt < 8; nt++) {
        int col = wc*64 + nt*8 + tg*2;
        float2 bb = *(const float2*)(bias + col);
        #pragma unroll
        for (int h = 0; h < 2; h++) {
            int r = row0 + rl0 + h*8;
            float2 fa = (r < LA) ? *(const float2*)(Ab + (long)r*H + col)
                                 : make_float2(0.f, 0.f);
            float o0 = acc[nt][2*h  ] + bb.x + fa.x;
            float o1 = acc[nt][2*h+1] + bb.y + fa.y;
            acc[nt][2*h] = o0; acc[nt][2*h+1] = o1;
            s[h] += o0 + o1;
            q[h] += o0*o0 + o1*o1;
        }
    }
    #pragma unroll
    for (int h = 0; h < 2; h++) {
        s[h] += __shfl_xor_sync(0xffffffffu, s[h], 1);
        s[h] += __shfl_xor_sync(0xffffffffu, s[h], 2);
        q[h] += __shfl_xor_sync(0xffffffffu, q[h], 1);
        q[h] += __shfl_xor_sync(0xffffffffu, q[h], 2);
    }
    if (tg == 0) {
        atomicAdd(&ssum[rl0    ], s[0]);
        atomicAdd(&ssq [rl0    ], q[0]);
        atomicAdd(&ssum[rl0 + 8], s[1]);
        atomicAdd(&ssq [rl0 + 8], q[1]);
    }
    __syncthreads();

    #pragma unroll
    for (int h = 0; h < 2; h++) {
        int rl = rl0 + h*8;
        int r = row0 + rl;
        float mu = ssum[rl] * (1.0f/H);
        float var = ssq[rl] * (1.0f/H) - mu*mu;
        float rstd = rsqrtf(var + 1e-5f);
        if (r < LA) {
            float* orow = out + ((long)b*LA + r)*H;
            #pragma unroll
            for (int nt = 0; nt < 8; nt++) {
                int col = wc*64 + nt*8 + tg*2;
                float2 gg = *(const float2*)(gamma + col);
                float2 be = *(const float2*)(beta + col);
                float2 o;
                o.x = (acc[nt][2*h  ] - mu)*rstd*gg.x + be.x;
                o.y = (acc[nt][2*h+1] - mu)*rstd*gg.y + be.y;
                *(float2*)(orow + col) = o;
            }
        }
    }
}

// ---------------- launch ----------------
extern "C" void kernel_launch(void* const* d_in, const int* in_sizes, int n_in,
                              void* d_out, int out_size) {
    const float* feat_a = (const float*)d_in[0];
    const float* feat_b = (const float*)d_in[1];
    const float* W      = (const float*)d_in[2];
    const float* bias   = (const float*)d_in[3];
    const float* gamma  = (const float*)d_in[4];
    const float* beta   = (const float*)d_in[5];
    float* out = (float*)d_out;

    static bool attr_done = false;
    if (!attr_done) {
        cudaFuncSetAttribute(k_wgemm_mma, cudaFuncAttributeMaxDynamicSharedMemorySize, WM_SMEM);
        cudaFuncSetAttribute(k_gemm2_ln, cudaFuncAttributeMaxDynamicSharedMemorySize, G2_SMEM);
        attr_done = true;
    }

    k_bmean_part<<<dim3(16,32), 128>>>(feat_b);
    k_bmean_red<<<32, 512>>>();
    k_wgemm_mma<<<1024, 256, WM_SMEM>>>(W);
    k_gemm2_ln<<<dim3(10,32), 512, G2_SMEM>>>(feat_a, bias, gamma, beta, out);
}

// round 8
// speedup vs baseline: 1.2593x; 1.2593x over previous
#include <cuda_runtime.h>
#include <cstdint>

#define BS 32
#define LA 300
#define LB 1024
#define H  512
#define NROW (H*H)

// ---------------- scratch ----------------
__device__ float g_part[BS*16*H];
__device__ float g_bm[BS*H];               // b_mean [b][e]
__device__ float g_T[(long)BS*NROW];       // [b][k*H+d], pre-rounded tf32
__device__ float g_Apre[(long)BS*LA*H];    // feat_a pre-rounded tf32 (19.7MB)

// ---------------- helpers ----------------
__device__ __forceinline__ uint32_t f2tf(float f) {
    uint32_t r;
    asm("cvt.rna.tf32.f32 %0, %1;" : "=r"(r) : "f"(f));
    return r;
}
__device__ __forceinline__ void mma_tf32(float* c, uint32_t a0, uint32_t a1,
                                         uint32_t a2, uint32_t a3,
                                         uint32_t b0, uint32_t b1) {
    asm volatile("mma.sync.aligned.m16n8k8.row.col.f32.tf32.tf32.f32 "
                 "{%0,%1,%2,%3}, {%4,%5,%6,%7}, {%8,%9}, {%0,%1,%2,%3};"
                 : "+f"(c[0]), "+f"(c[1]), "+f"(c[2]), "+f"(c[3])
                 : "r"(a0), "r"(a1), "r"(a2), "r"(a3), "r"(b0), "r"(b1));
}

// ---------------- kernel 1: b_mean (coalesced) ----------------
__global__ void k_bmean_part(const float* __restrict__ feat_b) {
    int chunk = blockIdx.x, b = blockIdx.y, t = threadIdx.x;
    const float4* p = (const float4*)(feat_b + ((long)b*LB + (long)chunk*64)*H) + t;
    float4 s = make_float4(0.f,0.f,0.f,0.f);
    #pragma unroll 8
    for (int j = 0; j < 64; j++) {
        float4 v = __ldg(p + (long)j*128);
        s.x += v.x; s.y += v.y; s.z += v.z; s.w += v.w;
    }
    *((float4*)(g_part + ((long)b*16 + chunk)*H) + t) = s;
}
__global__ void k_bmean_red() {
    long idx = (long)blockIdx.x*512 + threadIdx.x;
    long b = idx >> 9, d = idx & 511;
    float s = 0.f;
    #pragma unroll
    for (int c = 0; c < 16; c++) s += g_part[(b*16 + c)*H + d];
    g_bm[idx] = s * (1.0f/1024.0f);
}

// ---------------- kernel 1c: pre-round feat_a to tf32 ----------------
__global__ void k_around(const float* __restrict__ A) {
    long i = (long)blockIdx.x*256 + threadIdx.x;     // float4 index
    float4 v = __ldg((const float4*)A + i);
    uint4 t;
    t.x = f2tf(v.x); t.y = f2tf(v.y); t.z = f2tf(v.z); t.w = f2tf(v.w);
    *((uint4*)g_Apre + i) = t;
}

// ---------------- kernel 2: T[b][r] = W2d x bm^T via mma.sync tf32 ----------------
// [R6-proven] CTA 256 thr / 8 warps, 128 rows, K=512 in 32 chunks of 16.
// + 2-chunk register prefetch of A (4 LDG.128 in flight per thread).
#define SBM 528
#define WM_SMEM (32*SBM*4 + 16384)   // 67584 + 16384 sD

__global__ void __launch_bounds__(256) k_wgemm_mma(const float* __restrict__ Wg) {
    extern __shared__ char smem[];
    uint32_t* sB = (uint32_t*)smem;            // [32][528] tf32 bits
    float* sD = (float*)(smem + 32*SBM*4);     // [32][128]

    int tid = threadIdx.x;
    int wid = tid >> 5, lane = tid & 31;
    int group = lane >> 2, tg = lane & 3;
    long r0 = (long)blockIdx.x * 128;
    int m0 = wid * 16;

    for (int i = tid; i < 32*128; i += 256) {
        int n = i >> 7, k4 = i & 127;
        float4 v = __ldg((const float4*)g_bm + n*128 + k4);
        uint4 t;
        t.x = f2tf(v.x); t.y = f2tf(v.y); t.z = f2tf(v.z); t.w = f2tf(v.w);
        *(uint4*)(sB + n*SBM + k4*4) = t;
    }
    __syncthreads();

    const float4* A0 = (const float4*)(Wg + (long)(r0 + m0 + group)*H) + tg;
    const float4* A1 = A0 + 1024;     // +8 rows

    float acc[4][4];
    #pragma unroll
    for (int i = 0; i < 4; i++)
        #pragma unroll
        for (int j = 0; j < 4; j++) acc[i][j] = 0.f;

    float4 pw0[2], pw1[2];
    pw0[0] = __ldg(A0);       pw1[0] = __ldg(A1);
    pw0[1] = __ldg(A0 + 4);   pw1[1] = __ldg(A1 + 4);

    #pragma unroll 2
    for (int c = 0; c < 32; c++) {
        float4 w0 = pw0[c & 1], w1 = pw1[c & 1];
        if (c + 2 < 32) {
            pw0[c & 1] = __ldg(A0 + (c+2)*4);
            pw1[c & 1] = __ldg(A1 + (c+2)*4);
        }
        uint32_t ax0 = f2tf(w0.x), ax1 = f2tf(w1.x);
        uint32_t ay0 = f2tf(w0.y), ay1 = f2tf(w1.y);
        uint32_t az0 = f2tf(w0.z), az1 = f2tf(w1.z);
        uint32_t aw0 = f2tf(w0.w), aw1 = f2tf(w1.w);
        #pragma unroll
        for (int nt = 0; nt < 4; nt++) {
            uint4 bv = *(const uint4*)(sB + (nt*8 + group)*SBM + c*16 + tg*4);
            mma_tf32(acc[nt], ax0, ax1, ay0, ay1, bv.x, bv.y);
            mma_tf32(acc[nt], az0, az1, aw0, aw1, bv.z, bv.w);
        }
    }

    #pragma unroll
    for (int nt = 0; nt < 4; nt++) {
        int n0 = nt*8 + tg*2;
        int rl = m0 + group;
        sD[(n0  )*128 + rl    ] = acc[nt][0];
        sD[(n0+1)*128 + rl    ] = acc[nt][1];
        sD[(n0  )*128 + rl + 8] = acc[nt][2];
        sD[(n0+1)*128 + rl + 8] = acc[nt][3];
    }
    __syncthreads();
    #pragma unroll
    for (int p = 0; p < 16; p++) {
        int i = p*256 + tid;
        int n = i >> 7, rl = i & 127;
        uint32_t t = f2tf(sD[i]);           // pre-round for gemm2 B
        g_T[(long)n*NROW + r0 + rl] = __uint_as_float(t);
    }
}

// ---------------- kernel 3: fused = feat_a @ T^T (+bias +feat_a) via mma ----------
// [R6-proven tiling] tile 64x128, 8 warps, 4-stage cp.async; A from g_Apre (no cvt).
#define G2_STG   12288
#define G2_SMEM  (4*G2_STG)

__global__ void __launch_bounds__(256) k_gemm2(const float* __restrict__ Araw,
                                               const float* __restrict__ bias,
                                               float* __restrict__ out) {
    extern __shared__ char smem[];
    int b = blockIdx.z, kt = blockIdx.y, mt = blockIdx.x;
    int tid = threadIdx.x;
    int wid = tid >> 5, lane = tid & 31;
    int group = lane >> 2, tg = lane & 3;
    int wm = wid & 3, wc = wid >> 2;
    int row0 = mt * 64;
    const float* Ab  = Araw  + (long)b*LA*H;       // residual (fp32)
    const float* Abp = g_Apre + (long)b*LA*H;      // mma A (tf32 bits)
    const float* Bb  = g_T + (long)b*NROW + (long)kt*128*H;

    auto issue = [&](int c) {
        char* st = smem + (c & 3)*G2_STG;
        {
            int row = tid >> 2, i = tid & 3;
            const float* src = Abp + (long)(row0 + row)*H + c*16 + i*4;
            unsigned dst = (unsigned)__cvta_generic_to_shared(st + row*64 + i*16);
            int vsz = (row0 + row < LA) ? 16 : 0;
            asm volatile("cp.async.cg.shared.global [%0], [%1], 16, %2;"
                         :: "r"(dst), "l"(src), "r"(vsz));
        }
        #pragma unroll
        for (int q = 0; q < 2; q++) {
            int g2 = q*256 + tid;
            int row = g2 >> 2, i = g2 & 3;
            const float* src = Bb + (long)row*H + c*16 + i*4;
            unsigned dst = (unsigned)__cvta_generic_to_shared(st + 4096 + row*64 + i*16);
            asm volatile("cp.async.cg.shared.global [%0], [%1], 16;"
                         :: "r"(dst), "l"(src));
        }
        asm volatile("cp.async.commit_group;" ::: "memory");
    };

    issue(0); issue(1); issue(2);

    float acc[8][4];
    #pragma unroll
    for (int i = 0; i < 8; i++)
        #pragma unroll
        for (int j = 0; j < 4; j++) acc[i][j] = 0.f;

    for (int c = 0; c < 32; c++) {
        asm volatile("cp.async.wait_group 2;" ::: "memory");
        __syncthreads();
        if (c + 3 < 32) issue(c + 3);

        const char* st = smem + (c & 3)*G2_STG;
        const uint32_t* sA = (const uint32_t*)st;
        const uint32_t* sBt = (const uint32_t*)(st + 4096);

        uint4 a0v = *(const uint4*)(sA + (wm*16 + group)*16 + tg*4);
        uint4 a1v = *(const uint4*)(sA + (wm*16 + group + 8)*16 + tg*4);
        #pragma unroll
        for (int nt = 0; nt < 8; nt++) {
            uint4 bv = *(const uint4*)(sBt + (wc*64 + nt*8 + group)*16 + tg*4);
            mma_tf32(acc[nt], a0v.x, a1v.x, a0v.y, a1v.y, bv.x, bv.y);
            mma_tf32(acc[nt], a0v.z, a1v.z, a0v.w, a1v.w, bv.z, bv.w);
        }
        __syncthreads();
    }

    int grow = row0 + wm*16 + group;
    #pragma unroll
    for (int nt = 0; nt < 8; nt++) {
        int col = kt*128 + wc*64 + nt*8 + tg*2;
        float2 bb = *(const float2*)(bias + col);
        #pragma unroll
        for (int h = 0; h < 2; h++) {
            int r = grow + h*8;
            if (r < LA) {
                float2 fa = *(const float2*)(Ab + (long)r*H + col);
                float2 o;
                o.x = acc[nt][h*2+0] + bb.x + fa.x;
                o.y = acc[nt][h*2+1] + bb.y + fa.y;
                *(float2*)(out + ((long)b*LA + r)*H + col) = o;
            }
        }
    }
}

// ---------------- kernel 4: LayerNorm in-place ----------------
__global__ void k_ln(const float* __restrict__ gamma, const float* __restrict__ beta,
                     float* __restrict__ out) {
    __shared__ float ssum[4], ssq[4];
    long row = blockIdx.x;
    int tid = threadIdx.x;
    float4* xr = reinterpret_cast<float4*>(out + row*H);
    float4 v = xr[tid];
    float s  = v.x + v.y + v.z + v.w;
    float sq = v.x*v.x + v.y*v.y + v.z*v.z + v.w*v.w;
    #pragma unroll
    for (int o = 16; o > 0; o >>= 1) {
        s  += __shfl_xor_sync(0xffffffffu, s,  o);
        sq += __shfl_xor_sync(0xffffffffu, sq, o);
    }
    int wid = tid >> 5;
    if ((tid & 31) == 0) { ssum[wid] = s; ssq[wid] = sq; }
    __syncthreads();
    float stot = ssum[0] + ssum[1] + ssum[2] + ssum[3];
    float sqtot = ssq[0] + ssq[1] + ssq[2] + ssq[3];
    float mu = stot * (1.0f/H);
    float var = sqtot * (1.0f/H) - mu*mu;
    float rstd = rsqrtf(var + 1e-5f);
    const float4 g4 = reinterpret_cast<const float4*>(gamma)[tid];
    const float4 b4 = reinterpret_cast<const float4*>(beta)[tid];
    v.x = (v.x - mu)*rstd*g4.x + b4.x;
    v.y = (v.y - mu)*rstd*g4.y + b4.y;
    v.z = (v.z - mu)*rstd*g4.z + b4.z;
    v.w = (v.w - mu)*rstd*g4.w + b4.w;
    xr[tid] = v;
}

// ---------------- launch ----------------
extern "C" void kernel_launch(void* const* d_in, const int* in_sizes, int n_in,
                              void* d_out, int out_size) {
    const float* feat_a = (const float*)d_in[0];
    const float* feat_b = (const float*)d_in[1];
    const float* W      = (const float*)d_in[2];
    const float* bias   = (const float*)d_in[3];
    const float* gamma  = (const float*)d_in[4];
    const float* beta   = (const float*)d_in[5];
    float* out = (float*)d_out;

    static bool attr_done = false;
    if (!attr_done) {
        cudaFuncSetAttribute(k_wgemm_mma, cudaFuncAttributeMaxDynamicSharedMemorySize, WM_SMEM);
        cudaFuncSetAttribute(k_gemm2, cudaFuncAttributeMaxDynamicSharedMemorySize, G2_SMEM);
        attr_done = true;
    }

    k_bmean_part<<<dim3(16,32), 128>>>(feat_b);
    k_bmean_red<<<32, 512>>>();
    k_around<<<(BS*LA*H/4 + 255)/256, 256>>>(feat_a);
    k_wgemm_mma<<<2048, 256, WM_SMEM>>>(W);
    k_gemm2<<<dim3(5,4,32), 256, G2_SMEM>>>(feat_a, bias, out);
    k_ln<<<9600, 128>>>(gamma, beta, out);
}

// round 9
// speedup vs baseline: 1.3053x; 1.0365x over previous
#include <cuda_runtime.h>
#include <cstdint>

#define BS 32
#define LA 300
#define LB 1024
#define H  512
#define NROW (H*H)

// ---------------- scratch ----------------
__device__ float g_part[BS*16*H];
__device__ float g_bm[BS*H];               // b_mean [b][e]
__device__ float g_T[(long)BS*NROW];       // [b][k*H+d], pre-rounded tf32
__device__ float g_Apre[(long)BS*LA*H];    // feat_a pre-rounded tf32

// ---------------- helpers ----------------
__device__ __forceinline__ uint32_t f2tf(float f) {
    uint32_t r;
    asm("cvt.rna.tf32.f32 %0, %1;" : "=r"(r) : "f"(f));
    return r;
}
__device__ __forceinline__ void mma_tf32(float* c, uint32_t a0, uint32_t a1,
                                         uint32_t a2, uint32_t a3,
                                         uint32_t b0, uint32_t b1) {
    asm volatile("mma.sync.aligned.m16n8k8.row.col.f32.tf32.tf32.f32 "
                 "{%0,%1,%2,%3}, {%4,%5,%6,%7}, {%8,%9}, {%0,%1,%2,%3};"
                 : "+f"(c[0]), "+f"(c[1]), "+f"(c[2]), "+f"(c[3])
                 : "r"(a0), "r"(a1), "r"(a2), "r"(a3), "r"(b0), "r"(b1));
}

// ---------------- kernel 1: b_mean (coalesced) ----------------
__global__ void k_bmean_part(const float* __restrict__ feat_b) {
    int chunk = blockIdx.x, b = blockIdx.y, t = threadIdx.x;
    const float4* p = (const float4*)(feat_b + ((long)b*LB + (long)chunk*64)*H) + t;
    float4 s = make_float4(0.f,0.f,0.f,0.f);
    #pragma unroll 8
    for (int j = 0; j < 64; j++) {
        float4 v = __ldg(p + (long)j*128);
        s.x += v.x; s.y += v.y; s.z += v.z; s.w += v.w;
    }
    *((float4*)(g_part + ((long)b*16 + chunk)*H) + t) = s;
}
__global__ void k_bmean_red() {
    long idx = (long)blockIdx.x*512 + threadIdx.x;
    long b = idx >> 9, d = idx & 511;
    float s = 0.f;
    #pragma unroll
    for (int c = 0; c < 16; c++) s += g_part[(b*16 + c)*H + d];
    g_bm[idx] = s * (1.0f/1024.0f);
}

// ---------------- kernel 1c: pre-round feat_a to tf32 ----------------
__global__ void k_around(const float* __restrict__ A) {
    long i = (long)blockIdx.x*256 + threadIdx.x;
    float4 v = __ldg((const float4*)A + i);
    uint4 t;
    t.x = f2tf(v.x); t.y = f2tf(v.y); t.z = f2tf(v.z); t.w = f2tf(v.w);
    *((uint4*)g_Apre + i) = t;
}

// ---------------- kernel 2: T[b][r] = W2d x bm^T via mma.sync tf32 ----------------
// CTA 256 thr / 8 warps, 128 rows, K=512 in 32 chunks of 16.
// sD ALIASES sB (used only after mainloop) -> smem 67.6KB -> 3 CTA/SM.
#define SBM 528
#define SDW 132
#define WM_SMEM (32*SBM*4)   // 67584

__global__ void __launch_bounds__(256, 3) k_wgemm_mma(const float* __restrict__ Wg) {
    extern __shared__ char smem[];
    uint32_t* sB = (uint32_t*)smem;            // [32][528] tf32 bits (mainloop)
    float* sD = (float*)smem;                  // [32][132] (epilogue, aliased)

    int tid = threadIdx.x;
    int wid = tid >> 5, lane = tid & 31;
    int group = lane >> 2, tg = lane & 3;
    long r0 = (long)blockIdx.x * 128;
    int m0 = wid * 16;

    for (int i = tid; i < 32*128; i += 256) {
        int n = i >> 7, k4 = i & 127;
        float4 v = __ldg((const float4*)g_bm + n*128 + k4);
        uint4 t;
        t.x = f2tf(v.x); t.y = f2tf(v.y); t.z = f2tf(v.z); t.w = f2tf(v.w);
        *(uint4*)(sB + n*SBM + k4*4) = t;
    }
    __syncthreads();

    const float4* A0 = (const float4*)(Wg + (long)(r0 + m0 + group)*H) + tg;
    const float4* A1 = A0 + 1024;     // +8 rows

    float acc[4][4];
    #pragma unroll
    for (int i = 0; i < 4; i++)
        #pragma unroll
        for (int j = 0; j < 4; j++) acc[i][j] = 0.f;

    float4 pw0[2], pw1[2];
    pw0[0] = __ldg(A0);       pw1[0] = __ldg(A1);
    pw0[1] = __ldg(A0 + 4);   pw1[1] = __ldg(A1 + 4);

    #pragma unroll 2
    for (int c = 0; c < 32; c++) {
        float4 w0 = pw0[c & 1], w1 = pw1[c & 1];
        if (c + 2 < 32) {
            pw0[c & 1] = __ldg(A0 + (c+2)*4);
            pw1[c & 1] = __ldg(A1 + (c+2)*4);
        }
        uint32_t ax0 = f2tf(w0.x), ax1 = f2tf(w1.x);
        uint32_t ay0 = f2tf(w0.y), ay1 = f2tf(w1.y);
        uint32_t az0 = f2tf(w0.z), az1 = f2tf(w1.z);
        uint32_t aw0 = f2tf(w0.w), aw1 = f2tf(w1.w);
        #pragma unroll
        for (int nt = 0; nt < 4; nt++) {
            uint4 bv = *(const uint4*)(sB + (nt*8 + group)*SBM + c*16 + tg*4);
            mma_tf32(acc[nt], ax0, ax1, ay0, ay1, bv.x, bv.y);
            mma_tf32(acc[nt], az0, az1, aw0, aw1, bv.z, bv.w);
        }
    }

    __syncthreads();   // sB fully consumed; safe to alias as sD
    #pragma unroll
    for (int nt = 0; nt < 4; nt++) {
        int n0 = nt*8 + tg*2;
        int rl = m0 + group;
        sD[(n0  )*SDW + rl    ] = acc[nt][0];
        sD[(n0+1)*SDW + rl    ] = acc[nt][1];
        sD[(n0  )*SDW + rl + 8] = acc[nt][2];
        sD[(n0+1)*SDW + rl + 8] = acc[nt][3];
    }
    __syncthreads();
    #pragma unroll
    for (int p = 0; p < 16; p++) {
        int i = p*256 + tid;
        int n = i >> 7, rl = i & 127;
        uint32_t t = f2tf(sD[n*SDW + rl]);     // pre-round for gemm2 B
        g_T[(long)n*NROW + r0 + rl] = __uint_as_float(t);
    }
}

// ---------------- kernel 3: fused = feat_a @ T^T (+bias +feat_a) via mma ----------
#define G2_STG   12288
#define G2_SMEM  (4*G2_STG)

__global__ void __launch_bounds__(256) k_gemm2(const float* __restrict__ Araw,
                                               const float* __restrict__ bias,
                                               float* __restrict__ out) {
    extern __shared__ char smem[];
    int b = blockIdx.z, kt = blockIdx.y, mt = blockIdx.x;
    int tid = threadIdx.x;
    int wid = tid >> 5, lane = tid & 31;
    int group = lane >> 2, tg = lane & 3;
    int wm = wid & 3, wc = wid >> 2;
    int row0 = mt * 64;
    const float* Ab  = Araw  + (long)b*LA*H;
    const float* Abp = g_Apre + (long)b*LA*H;
    const float* Bb  = g_T + (long)b*NROW + (long)kt*128*H;

    auto issue = [&](int c) {
        char* st = smem + (c & 3)*G2_STG;
        {
            int row = tid >> 2, i = tid & 3;
            const float* src = Abp + (long)(row0 + row)*H + c*16 + i*4;
            unsigned dst = (unsigned)__cvta_generic_to_shared(st + row*64 + i*16);
            int vsz = (row0 + row < LA) ? 16 : 0;
            asm volatile("cp.async.cg.shared.global [%0], [%1], 16, %2;"
                         :: "r"(dst), "l"(src), "r"(vsz));
        }
        #pragma unroll
        for (int q = 0; q < 2; q++) {
            int g2 = q*256 + tid;
            int row = g2 >> 2, i = g2 & 3;
            const float* src = Bb + (long)row*H + c*16 + i*4;
            unsigned dst = (unsigned)__cvta_generic_to_shared(st + 4096 + row*64 + i*16);
            asm volatile("cp.async.cg.shared.global [%0], [%1], 16;"
                         :: "r"(dst), "l"(src));
        }
        asm volatile("cp.async.commit_group;" ::: "memory");
    };

    issue(0); issue(1); issue(2);

    float acc[8][4];
    #pragma unroll
    for (int i = 0; i < 8; i++)
        #pragma unroll
        for (int j = 0; j < 4; j++) acc[i][j] = 0.f;

    for (int c = 0; c < 32; c++) {
        asm volatile("cp.async.wait_group 2;" ::: "memory");
        __syncthreads();
        if (c + 3 < 32) issue(c + 3);

        const char* st = smem + (c & 3)*G2_STG;
        const uint32_t* sA = (const uint32_t*)st;
        const uint32_t* sBt = (const uint32_t*)(st + 4096);

        uint4 a0v = *(const uint4*)(sA + (wm*16 + group)*16 + tg*4);
        uint4 a1v = *(const uint4*)(sA + (wm*16 + group + 8)*16 + tg*4);
        #pragma unroll
        for (int nt = 0; nt < 8; nt++) {
            uint4 bv = *(const uint4*)(sBt + (wc*64 + nt*8 + group)*16 + tg*4);
            mma_tf32(acc[nt], a0v.x, a1v.x, a0v.y, a1v.y, bv.x, bv.y);
            mma_tf32(acc[nt], a0v.z, a1v.z, a0v.w, a1v.w, bv.z, bv.w);
        }
        __syncthreads();
    }

    int grow = row0 + wm*16 + group;
    #pragma unroll
    for (int nt = 0; nt < 8; nt++) {
        int col = kt*128 + wc*64 + nt*8 + tg*2;
        float2 bb = *(const float2*)(bias + col);
        #pragma unroll
        for (int h = 0; h < 2; h++) {
            int r = grow + h*8;
            if (r < LA) {
                float2 fa = *(const float2*)(Ab + (long)r*H + col);
                float2 o;
                o.x = acc[nt][h*2+0] + bb.x + fa.x;
                o.y = acc[nt][h*2+1] + bb.y + fa.y;
                *(float2*)(out + ((long)b*LA + r)*H + col) = o;
            }
        }
    }
}

// ---------------- kernel 4: LayerNorm in-place ----------------
__global__ void k_ln(const float* __restrict__ gamma, const float* __restrict__ beta,
                     float* __restrict__ out) {
    __shared__ float ssum[4], ssq[4];
    long row = blockIdx.x;
    int tid = threadIdx.x;
    float4* xr = reinterpret_cast<float4*>(out + row*H);
    float4 v = xr[tid];
    float s  = v.x + v.y + v.z + v.w;
    float sq = v.x*v.x + v.y*v.y + v.z*v.z + v.w*v.w;
    #pragma unroll
    for (int o = 16; o > 0; o >>= 1) {
        s  += __shfl_xor_sync(0xffffffffu, s,  o);
        sq += __shfl_xor_sync(0xffffffffu, sq, o);
    }
    int wid = tid >> 5;
    if ((tid & 31) == 0) { ssum[wid] = s; ssq[wid] = sq; }
    __syncthreads();
    float stot = ssum[0] + ssum[1] + ssum[2] + ssum[3];
    float sqtot = ssq[0] + ssq[1] + ssq[2] + ssq[3];
    float mu = stot * (1.0f/H);
    float var = sqtot * (1.0f/H) - mu*mu;
    float rstd = rsqrtf(var + 1e-5f);
    const float4 g4 = reinterpret_cast<const float4*>(gamma)[tid];
    const float4 b4 = reinterpret_cast<const float4*>(beta)[tid];
    v.x = (v.x - mu)*rstd*g4.x + b4.x;
    v.y = (v.y - mu)*rstd*g4.y + b4.y;
    v.z = (v.z - mu)*rstd*g4.z + b4.z;
    v.w = (v.w - mu)*rstd*g4.w + b4.w;
    xr[tid] = v;
}

// ---------------- launch ----------------
extern "C" void kernel_launch(void* const* d_in, const int* in_sizes, int n_in,
                              void* d_out, int out_size) {
    const float* feat_a = (const float*)d_in[0];
    const float* feat_b = (const float*)d_in[1];
    const float* W      = (const float*)d_in[2];
    const float* bias   = (const float*)d_in[3];
    const float* gamma  = (const float*)d_in[4];
    const float* beta   = (const float*)d_in[5];
    float* out = (float*)d_out;

    static bool attr_done = false;
    if (!attr_done) {
        cudaFuncSetAttribute(k_wgemm_mma, cudaFuncAttributeMaxDynamicSharedMemorySize, WM_SMEM);
        cudaFuncSetAttribute(k_gemm2, cudaFuncAttributeMaxDynamicSharedMemorySize, G2_SMEM);
        attr_done = true;
    }

    k_bmean_part<<<dim3(16,32), 128>>>(feat_b);
    k_bmean_red<<<32, 512>>>();
    k_around<<<(BS*LA*H/4 + 255)/256, 256>>>(feat_a);
    k_wgemm_mma<<<2048, 256, WM_SMEM>>>(W);
    k_gemm2<<<dim3(5,4,32), 256, G2_SMEM>>>(feat_a, bias, out);
    k_ln<<<9600, 128>>>(gamma, beta, out);
}

// round 12
// speedup vs baseline: 1.5283x; 1.1708x over previous
#include <cuda_runtime.h>
#include <cstdint>

#define BS 32
#define LA 300
#define LB 1024
#define H  512
#define NROW (H*H)

// ---------------- scratch ----------------
__device__ float g_part[BS*16*H];
__device__ float g_bm[BS*H];               // b_mean [b][e]
__device__ uint2 g_bfrag[8192];            // fragment-ordered tf32 B blob (64KB)
__device__ float g_T[(long)BS*NROW];       // [b][k*H+d], pre-rounded tf32
__device__ float g_Apre[(long)BS*LA*H];    // feat_a pre-rounded tf32

// ---------------- helpers ----------------
__device__ __forceinline__ uint32_t f2tf(float f) {
    uint32_t r;
    asm("cvt.rna.tf32.f32 %0, %1;" : "=r"(r) : "f"(f));
    return r;
}
__device__ __forceinline__ void mma_tf32(float* c, uint32_t a0, uint32_t a1,
                                         uint32_t a2, uint32_t a3,
                                         uint32_t b0, uint32_t b1) {
    asm volatile("mma.sync.aligned.m16n8k8.row.col.f32.tf32.tf32.f32 "
                 "{%0,%1,%2,%3}, {%4,%5,%6,%7}, {%8,%9}, {%0,%1,%2,%3};"
                 : "+f"(c[0]), "+f"(c[1]), "+f"(c[2]), "+f"(c[3])
                 : "r"(a0), "r"(a1), "r"(a2), "r"(a3), "r"(b0), "r"(b1));
}

// ---------------- kernel 1: b_mean (coalesced) ----------------
__global__ void k_bmean_part(const float* __restrict__ feat_b) {
    int chunk = blockIdx.x, b = blockIdx.y, t = threadIdx.x;
    const float4* p = (const float4*)(feat_b + ((long)b*LB + (long)chunk*64)*H) + t;
    float4 s = make_float4(0.f,0.f,0.f,0.f);
    #pragma unroll 8
    for (int j = 0; j < 64; j++) {
        float4 v = __ldg(p + (long)j*128);
        s.x += v.x; s.y += v.y; s.z += v.z; s.w += v.w;
    }
    *((float4*)(g_part + ((long)b*16 + chunk)*H) + t) = s;
}
__global__ void k_bmean_red() {
    long idx = (long)blockIdx.x*512 + threadIdx.x;
    long b = idx >> 9, d = idx & 511;
    float s = 0.f;
    #pragma unroll
    for (int c = 0; c < 16; c++) s += g_part[(b*16 + c)*H + d];
    g_bm[idx] = s * (1.0f/1024.0f);
}

// ---------------- kernel 1b: B fragment blob ----------------
// blob[((c*2+m)*4+nt)*32+lane] = {tf32(bm[n][k]), tf32(bm[n][k+1])},
// n = nt*8+(lane>>2), k = c*16+(lane&3)*4+m*2  — exact transcription of the
// bv.x..w mapping proven in R6-R9.
__global__ void k_bfrag() {
    int idx = blockIdx.x*256 + threadIdx.x;     // 8192
    int lane = idx & 31;
    int nt = (idx >> 5) & 3;
    int cm = idx >> 7;                          // c*2+m
    int c = cm >> 1, m = cm & 1;
    int n = nt*8 + (lane >> 2);
    int k = c*16 + (lane & 3)*4 + m*2;
    uint2 v;
    v.x = f2tf(g_bm[n*H + k]);
    v.y = f2tf(g_bm[n*H + k + 1]);
    g_bfrag[idx] = v;
}

// ---------------- kernel 1c: pre-round feat_a to tf32 ----------------
__global__ void k_around(const float* __restrict__ A) {
    long i = (long)blockIdx.x*256 + threadIdx.x;
    float4 v = __ldg((const float4*)A + i);
    uint4 t;
    t.x = f2tf(v.x); t.y = f2tf(v.y); t.z = f2tf(v.z); t.w = f2tf(v.w);
    *((uint4*)g_Apre + i) = t;
}

// ---------------- kernel 2: T[b][r] = W2d x bm^T via mma.sync tf32 ----------------
// CTA 256 thr / 8 warps, 128 rows, K=512 in 32 chunks of 16.
// A: 4-stage cp.async pipeline ([128][16] unpadded, conflict-free by phase).
// B: 64KB fragment blob cp.async'd once. smem 96KB -> 2 CTA/SM.
#define SDW 132
#define WM_SMEM (65536 + 4*8192)    // 98304

__global__ void __launch_bounds__(256, 2) k_wgemm_mma(const float* __restrict__ Wg) {
    extern __shared__ char smem[];
    uint2* sbf = (uint2*)smem;                 // [8192] B frags
    char* sStg = smem + 65536;                 // 4 stages x 8KB
    float* sD = (float*)smem;                  // epilogue aliases blob

    int tid = threadIdx.x;
    int wid = tid >> 5, lane = tid & 31;
    int group = lane >> 2, tg = lane & 3;
    long r0 = (long)blockIdx.x * 128;
    int m0 = wid * 16;

    // group 0: B blob (contiguous 64KB)
    {
        const char* src = (const char*)g_bfrag;
        uint32_t sb0 = (uint32_t)__cvta_generic_to_shared(smem);
        #pragma unroll
        for (int p = 0; p < 16; p++) {
            int i = p*256 + tid;
            asm volatile("cp.async.cg.shared.global [%0], [%1], 16;"
                         :: "r"(sb0 + i*16), "l"(src + (long)i*16));
        }
        asm volatile("cp.async.commit_group;" ::: "memory");
    }

    auto issue = [&](int c) {
        uint32_t st = (uint32_t)__cvta_generic_to_shared(sStg) + (c & 3)*8192;
        #pragma unroll
        for (int q = 0; q < 2; q++) {
            int g = q*256 + tid;
            int row = g >> 2, i = g & 3;
            const float* src = Wg + (r0 + row)*H + c*16 + i*4;
            asm volatile("cp.async.cg.shared.global [%0], [%1], 16;"
                         :: "r"(st + row*64 + i*16), "l"(src));
        }
        asm volatile("cp.async.commit_group;" ::: "memory");
    };
    issue(0); issue(1); issue(2); issue(3);

    float acc[4][4];
    #pragma unroll
    for (int i = 0; i < 4; i++)
        #pragma unroll
        for (int j = 0; j < 4; j++) acc[i][j] = 0.f;

    for (int c = 0; c < 32; c++) {
        if (c < 29)      asm volatile("cp.async.wait_group 3;" ::: "memory");
        else if (c == 29) asm volatile("cp.async.wait_group 2;" ::: "memory");
        else if (c == 30) asm volatile("cp.async.wait_group 1;" ::: "memory");
        else              asm volatile("cp.async.wait_group 0;" ::: "memory");
        __syncthreads();

        const uint32_t* sA = (const uint32_t*)(sStg + (c & 3)*8192);
        uint4 a0v = *(const uint4*)(sA + (m0 + group)*16 + tg*4);
        uint4 a1v = *(const uint4*)(sA + (m0 + group + 8)*16 + tg*4);
        uint32_t ax0 = f2tf(__uint_as_float(a0v.x)), ax1 = f2tf(__uint_as_float(a1v.x));
        uint32_t ay0 = f2tf(__uint_as_float(a0v.y)), ay1 = f2tf(__uint_as_float(a1v.y));
        uint32_t az0 = f2tf(__uint_as_float(a0v.z)), az1 = f2tf(__uint_as_float(a1v.z));
        uint32_t aw0 = f2tf(__uint_as_float(a0v.w)), aw1 = f2tf(__uint_as_float(a1v.w));

        const uint2* bb = sbf + c*8*32 + lane;
        #pragma unroll
        for (int nt = 0; nt < 4; nt++) {
            uint2 b0 = bb[nt*32];           // m=0
            uint2 b1 = bb[(4 + nt)*32];     // m=1
            mma_tf32(acc[nt], ax0, ax1, ay0, ay1, b0.x, b0.y);
            mma_tf32(acc[nt], az0, az1, aw0, aw1, b1.x, b1.y);
        }
        __syncthreads();
        if (c + 4 < 32) issue(c + 4);
    }

    // epilogue (sD aliases blob; all blob reads done)
    #pragma unroll
    for (int nt = 0; nt < 4; nt++) {
        int n0 = nt*8 + tg*2;
        int rl = m0 + group;
        sD[(n0  )*SDW + rl    ] = acc[nt][0];
        sD[(n0+1)*SDW + rl    ] = acc[nt][1];
        sD[(n0  )*SDW + rl + 8] = acc[nt][2];
        sD[(n0+1)*SDW + rl + 8] = acc[nt][3];
    }
    __syncthreads();
    #pragma unroll
    for (int p = 0; p < 16; p++) {
        int i = p*256 + tid;
        int n = i >> 7, rl = i & 127;
        uint32_t t = f2tf(sD[n*SDW + rl]);     // pre-round for gemm2 B
        g_T[(long)n*NROW + r0 + rl] = __uint_as_float(t);
    }
}

// ---------------- kernel 3: fused = feat_a @ T^T (+bias +feat_a) via mma ----------
#define G2_STG   12288
#define G2_SMEM  (4*G2_STG)

__global__ void __launch_bounds__(256) k_gemm2(const float* __restrict__ Araw,
                                               const float* __restrict__ bias,
                                               float* __restrict__ out) {
    extern __shared__ char smem[];
    int b = blockIdx.z, kt = blockIdx.y, mt = blockIdx.x;
    int tid = threadIdx.x;
    int wid = tid >> 5, lane = tid & 31;
    int group = lane >> 2, tg = lane & 3;
    int wm = wid & 3, wc = wid >> 2;
    int row0 = mt * 64;
    const float* Ab  = Araw  + (long)b*LA*H;
    const float* Abp = g_Apre + (long)b*LA*H;
    const float* Bb  = g_T + (long)b*NROW + (long)kt*128*H;

    auto issue = [&](int c) {
        char* st = smem + (c & 3)*G2_STG;
        {
            int row = tid >> 2, i = tid & 3;
            const float* src = Abp + (long)(row0 + row)*H + c*16 + i*4;
            unsigned dst = (unsigned)__cvta_generic_to_shared(st + row*64 + i*16);
            int vsz = (row0 + row < LA) ? 16 : 0;
            asm volatile("cp.async.cg.shared.global [%0], [%1], 16, %2;"
                         :: "r"(dst), "l"(src), "r"(vsz));
        }
        #pragma unroll
        for (int q = 0; q < 2; q++) {
            int g2 = q*256 + tid;
            int row = g2 >> 2, i = g2 & 3;
            const float* src = Bb + (long)row*H + c*16 + i*4;
            unsigned dst = (unsigned)__cvta_generic_to_shared(st + 4096 + row*64 + i*16);
            asm volatile("cp.async.cg.shared.global [%0], [%1], 16;"
                         :: "r"(dst), "l"(src));
        }
        asm volatile("cp.async.commit_group;" ::: "memory");
    };

    issue(0); issue(1); issue(2);

    float acc[8][4];
    #pragma unroll
    for (int i = 0; i < 8; i++)
        #pragma unroll
        for (int j = 0; j < 4; j++) acc[i][j] = 0.f;

    for (int c = 0; c < 32; c++) {
        asm volatile("cp.async.wait_group 2;" ::: "memory");
        __syncthreads();
        if (c + 3 < 32) issue(c + 3);

        const char* st = smem + (c & 3)*G2_STG;
        const uint32_t* sA = (const uint32_t*)st;
        const uint32_t* sBt = (const uint32_t*)(st + 4096);

        uint4 a0v = *(const uint4*)(sA + (wm*16 + group)*16 + tg*4);
        uint4 a1v = *(const uint4*)(sA + (wm*16 + group + 8)*16 + tg*4);
        #pragma unroll
        for (int nt = 0; nt < 8; nt++) {
            uint4 bv = *(const uint4*)(sBt + (wc*64 + nt*8 + group)*16 + tg*4);
            mma_tf32(acc[nt], a0v.x, a1v.x, a0v.y, a1v.y, bv.x, bv.y);
            mma_tf32(acc[nt], a0v.z, a1v.z, a0v.w, a1v.w, bv.z, bv.w);
        }
        __syncthreads();
    }

    int grow = row0 + wm*16 + group;
    #pragma unroll
    for (int nt = 0; nt < 8; nt++) {
        int col = kt*128 + wc*64 + nt*8 + tg*2;
        float2 bb = *(const float2*)(bias + col);
        #pragma unroll
        for (int h = 0; h < 2; h++) {
            int r = grow + h*8;
            if (r < LA) {
                float2 fa = *(const float2*)(Ab + (long)r*H + col);
                float2 o;
                o.x = acc[nt][h*2+0] + bb.x + fa.x;
                o.y = acc[nt][h*2+1] + bb.y + fa.y;
                *(float2*)(out + ((long)b*LA + r)*H + col) = o;
            }
        }
    }
}

// ---------------- kernel 4: LayerNorm in-place ----------------
__global__ void k_ln(const float* __restrict__ gamma, const float* __restrict__ beta,
                     float* __restrict__ out) {
    __shared__ float ssum[4], ssq[4];
    long row = blockIdx.x;
    int tid = threadIdx.x;
    float4* xr = reinterpret_cast<float4*>(out + row*H);
    float4 v = xr[tid];
    float s  = v.x + v.y + v.z + v.w;
    float sq = v.x*v.x + v.y*v.y + v.z*v.z + v.w*v.w;
    #pragma unroll
    for (int o = 16; o > 0; o >>= 1) {
        s  += __shfl_xor_sync(0xffffffffu, s,  o);
        sq += __shfl_xor_sync(0xffffffffu, sq, o);
    }
    int wid = tid >> 5;
    if ((tid & 31) == 0) { ssum[wid] = s; ssq[wid] = sq; }
    __syncthreads();
    float stot = ssum[0] + ssum[1] + ssum[2] + ssum[3];
    float sqtot = ssq[0] + ssq[1] + ssq[2] + ssq[3];
    float mu = stot * (1.0f/H);
    float var = sqtot * (1.0f/H) - mu*mu;
    float rstd = rsqrtf(var + 1e-5f);
    const float4 g4 = reinterpret_cast<const float4*>(gamma)[tid];
    const float4 b4 = reinterpret_cast<const float4*>(beta)[tid];
    v.x = (v.x - mu)*rstd*g4.x + b4.x;
    v.y = (v.y - mu)*rstd*g4.y + b4.y;
    v.z = (v.z - mu)*rstd*g4.z + b4.z;
    v.w = (v.w - mu)*rstd*g4.w + b4.w;
    xr[tid] = v;
}

// ---------------- launch ----------------
extern "C" void kernel_launch(void* const* d_in, const int* in_sizes, int n_in,
                              void* d_out, int out_size) {
    const float* feat_a = (const float*)d_in[0];
    const float* feat_b = (const float*)d_in[1];
    const float* W      = (const float*)d_in[2];
    const float* bias   = (const float*)d_in[3];
    const float* gamma  = (const float*)d_in[4];
    const float* beta   = (const float*)d_in[5];
    float* out = (float*)d_out;

    static bool attr_done = false;
    if (!attr_done) {
        cudaFuncSetAttribute(k_wgemm_mma, cudaFuncAttributeMaxDynamicSharedMemorySize, WM_SMEM);
        cudaFuncSetAttribute(k_gemm2, cudaFuncAttributeMaxDynamicSharedMemorySize, G2_SMEM);
        attr_done = true;
    }

    k_bmean_part<<<dim3(16,32), 128>>>(feat_b);
    k_bmean_red<<<32, 512>>>();
    k_bfrag<<<32, 256>>>();
    k_around<<<(BS*LA*H/4 + 255)/256, 256>>>(feat_a);
    k_wgemm_mma<<<2048, 256, WM_SMEM>>>(W);
    k_gemm2<<<dim3(5,4,32), 256, G2_SMEM>>>(feat_a, bias, out);
    k_ln<<<9600, 128>>>(gamma, beta, out);
}

// round 14
// speedup vs baseline: 1.5952x; 1.0438x over previous
#include <cuda_runtime.h>
#include <cstdint>

#define BS 32
#define LA 300
#define LB 1024
#define H  512
#define NROW (H*H)

// ---------------- scratch ----------------
__device__ float g_part[BS*16*H];
__device__ float g_bm[BS*H];               // b_mean [b][e]
__device__ uint2 g_bfrag[8192];            // fragment-ordered tf32 B blob (64KB)
__device__ float g_T[(long)BS*NROW];       // [b][k*H+d], pre-rounded tf32

// ---------------- helpers ----------------
__device__ __forceinline__ uint32_t f2tf(float f) {
    uint32_t r;
    asm("cvt.rna.tf32.f32 %0, %1;" : "=r"(r) : "f"(f));
    return r;
}
__device__ __forceinline__ void mma_tf32(float* c, uint32_t a0, uint32_t a1,
                                         uint32_t a2, uint32_t a3,
                                         uint32_t b0, uint32_t b1) {
    asm volatile("mma.sync.aligned.m16n8k8.row.col.f32.tf32.tf32.f32 "
                 "{%0,%1,%2,%3}, {%4,%5,%6,%7}, {%8,%9}, {%0,%1,%2,%3};"
                 : "+f"(c[0]), "+f"(c[1]), "+f"(c[2]), "+f"(c[3])
                 : "r"(a0), "r"(a1), "r"(a2), "r"(a3), "r"(b0), "r"(b1));
}

// ---------------- kernel 1: b_mean (coalesced) ----------------
__global__ void k_bmean_part(const float* __restrict__ feat_b) {
    int chunk = blockIdx.x, b = blockIdx.y, t = threadIdx.x;
    const float4* p = (const float4*)(feat_b + ((long)b*LB + (long)chunk*64)*H) + t;
    float4 s = make_float4(0.f,0.f,0.f,0.f);
    #pragma unroll 8
    for (int j = 0; j < 64; j++) {
        float4 v = __ldg(p + (long)j*128);
        s.x += v.x; s.y += v.y; s.z += v.z; s.w += v.w;
    }
    *((float4*)(g_part + ((long)b*16 + chunk)*H) + t) = s;
}
__global__ void k_bmean_red() {
    long idx = (long)blockIdx.x*512 + threadIdx.x;
    long b = idx >> 9, d = idx & 511;
    float s = 0.f;
    #pragma unroll
    for (int c = 0; c < 16; c++) s += g_part[(b*16 + c)*H + d];
    g_bm[idx] = s * (1.0f/1024.0f);
}

// ---------------- kernel 1b: B fragment blob ----------------
__global__ void k_bfrag() {
    int idx = blockIdx.x*256 + threadIdx.x;     // 8192
    int lane = idx & 31;
    int nt = (idx >> 5) & 3;
    int cm = idx >> 7;                          // c*2+m
    int c = cm >> 1, m = cm & 1;
    int n = nt*8 + (lane >> 2);
    int k = c*16 + (lane & 3)*4 + m*2;
    uint2 v;
    v.x = f2tf(g_bm[n*H + k]);
    v.y = f2tf(g_bm[n*H + k + 1]);
    g_bfrag[idx] = v;
}

// ---------------- kernel 2: T[b][r] = W2d x bm^T via mma.sync tf32 ----------------
// [R12-proven] CTA 256 thr / 8 warps, 128 rows, K=512 in 32 chunks of 16.
// A: 4-stage cp.async pipeline. B: 64KB fragment blob. smem 96KB -> 2 CTA/SM.
#define SDW 132
#define WM_SMEM (65536 + 4*8192)    // 98304

__global__ void __launch_bounds__(256, 2) k_wgemm_mma(const float* __restrict__ Wg) {
    extern __shared__ char smem[];
    uint2* sbf = (uint2*)smem;                 // [8192] B frags
    char* sStg = smem + 65536;                 // 4 stages x 8KB
    float* sD = (float*)smem;                  // epilogue aliases blob

    int tid = threadIdx.x;
    int wid = tid >> 5, lane = tid & 31;
    int group = lane >> 2, tg = lane & 3;
    long r0 = (long)blockIdx.x * 128;
    int m0 = wid * 16;

    // group 0: B blob (contiguous 64KB)
    {
        const char* src = (const char*)g_bfrag;
        uint32_t sb0 = (uint32_t)__cvta_generic_to_shared(smem);
        #pragma unroll
        for (int p = 0; p < 16; p++) {
            int i = p*256 + tid;
            asm volatile("cp.async.cg.shared.global [%0], [%1], 16;"
                         :: "r"(sb0 + i*16), "l"(src + (long)i*16));
        }
        asm volatile("cp.async.commit_group;" ::: "memory");
    }

    auto issue = [&](int c) {
        uint32_t st = (uint32_t)__cvta_generic_to_shared(sStg) + (c & 3)*8192;
        #pragma unroll
        for (int q = 0; q < 2; q++) {
            int g = q*256 + tid;
            int row = g >> 2, i = g & 3;
            const float* src = Wg + (r0 + row)*H + c*16 + i*4;
            asm volatile("cp.async.cg.shared.global [%0], [%1], 16;"
                         :: "r"(st + row*64 + i*16), "l"(src));
        }
        asm volatile("cp.async.commit_group;" ::: "memory");
    };
    issue(0); issue(1); issue(2); issue(3);

    float acc[4][4];
    #pragma unroll
    for (int i = 0; i < 4; i++)
        #pragma unroll
        for (int j = 0; j < 4; j++) acc[i][j] = 0.f;

    for (int c = 0; c < 32; c++) {
        if (c < 29)      asm volatile("cp.async.wait_group 3;" ::: "memory");
        else if (c == 29) asm volatile("cp.async.wait_group 2;" ::: "memory");
        else if (c == 30) asm volatile("cp.async.wait_group 1;" ::: "memory");
        else              asm volatile("cp.async.wait_group 0;" ::: "memory");
        __syncthreads();

        const uint32_t* sA = (const uint32_t*)(sStg + (c & 3)*8192);
        uint4 a0v = *(const uint4*)(sA + (m0 + group)*16 + tg*4);
        uint4 a1v = *(const uint4*)(sA + (m0 + group + 8)*16 + tg*4);
        uint32_t ax0 = f2tf(__uint_as_float(a0v.x)), ax1 = f2tf(__uint_as_float(a1v.x));
        uint32_t ay0 = f2tf(__uint_as_float(a0v.y)), ay1 = f2tf(__uint_as_float(a1v.y));
        uint32_t az0 = f2tf(__uint_as_float(a0v.z)), az1 = f2tf(__uint_as_float(a1v.z));
        uint32_t aw0 = f2tf(__uint_as_float(a0v.w)), aw1 = f2tf(__uint_as_float(a1v.w));

        const uint2* bb = sbf + c*8*32 + lane;
        #pragma unroll
        for (int nt = 0; nt < 4; nt++) {
            uint2 b0 = bb[nt*32];           // m=0
            uint2 b1 = bb[(4 + nt)*32];     // m=1
            mma_tf32(acc[nt], ax0, ax1, ay0, ay1, b0.x, b0.y);
            mma_tf32(acc[nt], az0, az1, aw0, aw1, b1.x, b1.y);
        }
        __syncthreads();
        if (c + 4 < 32) issue(c + 4);
    }

    // epilogue (sD aliases blob; all blob reads done)
    #pragma unroll
    for (int nt = 0; nt < 4; nt++) {
        int n0 = nt*8 + tg*2;
        int rl = m0 + group;
        sD[(n0  )*SDW + rl    ] = acc[nt][0];
        sD[(n0+1)*SDW + rl    ] = acc[nt][1];
        sD[(n0  )*SDW + rl + 8] = acc[nt][2];
        sD[(n0+1)*SDW + rl + 8] = acc[nt][3];
    }
    __syncthreads();
    #pragma unroll
    for (int p = 0; p < 16; p++) {
        int i = p*256 + tid;
        int n = i >> 7, rl = i & 127;
        uint32_t t = f2tf(sD[n*SDW + rl]);     // pre-round for gemm2 B
        g_T[(long)n*NROW + r0 + rl] = __uint_as_float(t);
    }
}

// ---------------- kernel 3: fused = feat_a @ T^T (+bias +feat_a) via mma ----------
// [R6-proven] tile 64x128, 8 warps, 4-stage cp.async, in-loop A cvt.
#define G2_STG   12288
#define G2_SMEM  (4*G2_STG)

__global__ void __launch_bounds__(256) k_gemm2(const float* __restrict__ Araw,
                                               const float* __restrict__ bias,
                                               float* __restrict__ out) {
    extern __shared__ char smem[];
    int b = blockIdx.z, kt = blockIdx.y, mt = blockIdx.x;
    int tid = threadIdx.x;
    int wid = tid >> 5, lane = tid & 31;
    int group = lane >> 2, tg = lane & 3;
    int wm = wid & 3, wc = wid >> 2;
    int row0 = mt * 64;
    const float* Ab = Araw + (long)b*LA*H;
    const float* Bb = g_T + (long)b*NROW + (long)kt*128*H;

    auto issue = [&](int c) {
        char* st = smem + (c & 3)*G2_STG;
        {
            int row = tid >> 2, i = tid & 3;
            const float* src = Ab + (long)(row0 + row)*H + c*16 + i*4;
            unsigned dst = (unsigned)__cvta_generic_to_shared(st + row*64 + i*16);
            int vsz = (row0 + row < LA) ? 16 : 0;
            asm volatile("cp.async.cg.shared.global [%0], [%1], 16, %2;"
                         :: "r"(dst), "l"(src), "r"(vsz));
        }
        #pragma unroll
        for (int q = 0; q < 2; q++) {
            int g2 = q*256 + tid;
            int row = g2 >> 2, i = g2 & 3;
            const float* src = Bb + (long)row*H + c*16 + i*4;
            unsigned dst = (unsigned)__cvta_generic_to_shared(st + 4096 + row*64 + i*16);
            asm volatile("cp.async.cg.shared.global [%0], [%1], 16;"
                         :: "r"(dst), "l"(src));
        }
        asm volatile("cp.async.commit_group;" ::: "memory");
    };

    issue(0); issue(1); issue(2);

    float acc[8][4];
    #pragma unroll
    for (int i = 0; i < 8; i++)
        #pragma unroll
        for (int j = 0; j < 4; j++) acc[i][j] = 0.f;

    for (int c = 0; c < 32; c++) {
        asm volatile("cp.async.wait_group 2;" ::: "memory");
        __syncthreads();
        if (c + 3 < 32) issue(c + 3);

        const char* st = smem + (c & 3)*G2_STG;
        const uint32_t* sA = (const uint32_t*)st;
        const uint32_t* sBt = (const uint32_t*)(st + 4096);

        uint4 a0v = *(const uint4*)(sA + (wm*16 + group)*16 + tg*4);
        uint4 a1v = *(const uint4*)(sA + (wm*16 + group + 8)*16 + tg*4);
        uint32_t ax0 = f2tf(__uint_as_float(a0v.x)), ax1 = f2tf(__uint_as_float(a1v.x));
        uint32_t ay0 = f2tf(__uint_as_float(a0v.y)), ay1 = f2tf(__uint_as_float(a1v.y));
        uint32_t az0 = f2tf(__uint_as_float(a0v.z)), az1 = f2tf(__uint_as_float(a1v.z));
        uint32_t aw0 = f2tf(__uint_as_float(a0v.w)), aw1 = f2tf(__uint_as_float(a1v.w));
        #pragma unroll
        for (int nt = 0; nt < 8; nt++) {
            uint4 bv = *(const uint4*)(sBt + (wc*64 + nt*8 + group)*16 + tg*4);
            mma_tf32(acc[nt], ax0, ax1, ay0, ay1, bv.x, bv.y);
            mma_tf32(acc[nt], az0, az1, aw0, aw1, bv.z, bv.w);
        }
        __syncthreads();
    }

    int grow = row0 + wm*16 + group;
    #pragma unroll
    for (int nt = 0; nt < 8; nt++) {
        int col = kt*128 + wc*64 + nt*8 + tg*2;
        float2 bb = *(const float2*)(bias + col);
        #pragma unroll
        for (int h = 0; h < 2; h++) {
            int r = grow + h*8;
            if (r < LA) {
                float2 fa = *(const float2*)(Ab + (long)r*H + col);
                float2 o;
                o.x = acc[nt][h*2+0] + bb.x + fa.x;
                o.y = acc[nt][h*2+1] + bb.y + fa.y;
                *(float2*)(out + ((long)b*LA + r)*H + col) = o;
            }
        }
    }
}

// ---------------- kernel 4: LayerNorm, warp-per-row (no smem, no bar) ----------
// grid 1200, 256 thr = 8 warps = 8 rows. 4 float4 per thread, shfl reduction.
__global__ void k_ln(const float* __restrict__ gamma, const float* __restrict__ beta,
                     float* __restrict__ out) {
    int wid = threadIdx.x >> 5, lane = threadIdx.x & 31;
    long row = (long)blockIdx.x*8 + wid;
    float4* xr = reinterpret_cast<float4*>(out + row*H);
    const float4* g4 = reinterpret_cast<const float4*>(gamma);
    const float4* b4 = reinterpret_cast<const float4*>(beta);

    float4 v[4];
    float s = 0.f, sq = 0.f;
    #pragma unroll
    for (int i = 0; i < 4; i++) {
        v[i] = xr[lane + i*32];
        s  += v[i].x + v[i].y + v[i].z + v[i].w;
        sq += v[i].x*v[i].x + v[i].y*v[i].y + v[i].z*v[i].z + v[i].w*v[i].w;
    }
    #pragma unroll
    for (int o = 16; o > 0; o >>= 1) {
        s  += __shfl_xor_sync(0xffffffffu, s,  o);
        sq += __shfl_xor_sync(0xffffffffu, sq, o);
    }
    float mu = s * (1.0f/H);
    float var = sq * (1.0f/H) - mu*mu;
    float rstd = rsqrtf(var + 1e-5f);
    #pragma unroll
    for (int i = 0; i < 4; i++) {
        float4 gg = __ldg(g4 + lane + i*32);
        float4 be = __ldg(b4 + lane + i*32);
        float4 o;
        o.x = (v[i].x - mu)*rstd*gg.x + be.x;
        o.y = (v[i].y - mu)*rstd*gg.y + be.y;
        o.z = (v[i].z - mu)*rstd*gg.z + be.z;
        o.w = (v[i].w - mu)*rstd*gg.w + be.w;
        xr[lane + i*32] = o;
    }
}

// ---------------- launch ----------------
extern "C" void kernel_launch(void* const* d_in, const int* in_sizes, int n_in,
                              void* d_out, int out_size) {
    const float* feat_a = (const float*)d_in[0];
    const float* feat_b = (const float*)d_in[1];
    const float* W      = (const float*)d_in[2];
    const float* bias   = (const float*)d_in[3];
    const float* gamma  = (const float*)d_in[4];
    const float* beta   = (const float*)d_in[5];
    float* out = (float*)d_out;

    static bool attr_done = false;
    if (!attr_done) {
        cudaFuncSetAttribute(k_wgemm_mma, cudaFuncAttributeMaxDynamicSharedMemorySize, WM_SMEM);
        cudaFuncSetAttribute(k_gemm2, cudaFuncAttributeMaxDynamicSharedMemorySize, G2_SMEM);
        attr_done = true;
    }

    k_bmean_part<<<dim3(16,32), 128>>>(feat_b);
    k_bmean_red<<<32, 512>>>();
    k_bfrag<<<32, 256>>>();
    k_wgemm_mma<<<2048, 256, WM_SMEM>>>(W);
    k_gemm2<<<dim3(5,4,32), 256, G2_SMEM>>>(feat_a, bias, out);
    k_ln<<<1200, 256>>>(gamma, beta, out);
}

// round 15
// speedup vs baseline: 1.6510x; 1.0350x over previous
#include <cuda_runtime.h>
#include <cstdint>

#define BS 32
#define LA 300
#define LB 1024
#define H  512
#define NROW (H*H)

// ---------------- scratch ----------------
__device__ float g_part[BS*16*H];
__device__ float g_bm[BS*H];               // b_mean [b][e]
__device__ uint2 g_bfrag[8192];            // fragment-ordered tf32 B blob (64KB)
__device__ float g_T[(long)BS*NROW];       // [b][k*H+d], pre-rounded tf32

// ---------------- helpers ----------------
__device__ __forceinline__ uint32_t f2tf(float f) {
    uint32_t r;
    asm("cvt.rna.tf32.f32 %0, %1;" : "=r"(r) : "f"(f));
    return r;
}
__device__ __forceinline__ void mma_tf32(float* c, uint32_t a0, uint32_t a1,
                                         uint32_t a2, uint32_t a3,
                                         uint32_t b0, uint32_t b1) {
    asm volatile("mma.sync.aligned.m16n8k8.row.col.f32.tf32.tf32.f32 "
                 "{%0,%1,%2,%3}, {%4,%5,%6,%7}, {%8,%9}, {%0,%1,%2,%3};"
                 : "+f"(c[0]), "+f"(c[1]), "+f"(c[2]), "+f"(c[3])
                 : "r"(a0), "r"(a1), "r"(a2), "r"(a3), "r"(b0), "r"(b1));
}

// ---------------- kernel 1: b_mean (coalesced) ----------------
__global__ void k_bmean_part(const float* __restrict__ feat_b) {
    int chunk = blockIdx.x, b = blockIdx.y, t = threadIdx.x;
    const float4* p = (const float4*)(feat_b + ((long)b*LB + (long)chunk*64)*H) + t;
    float4 s = make_float4(0.f,0.f,0.f,0.f);
    #pragma unroll 8
    for (int j = 0; j < 64; j++) {
        float4 v = __ldg(p + (long)j*128);
        s.x += v.x; s.y += v.y; s.z += v.z; s.w += v.w;
    }
    *((float4*)(g_part + ((long)b*16 + chunk)*H) + t) = s;
}
__global__ void k_bmean_red() {
    long idx = (long)blockIdx.x*512 + threadIdx.x;
    long b = idx >> 9, d = idx & 511;
    float s = 0.f;
    #pragma unroll
    for (int c = 0; c < 16; c++) s += g_part[(b*16 + c)*H + d];
    g_bm[idx] = s * (1.0f/1024.0f);
}

// ---------------- kernel 1b: B fragment blob ----------------
__global__ void k_bfrag() {
    int idx = blockIdx.x*256 + threadIdx.x;     // 8192
    int lane = idx & 31;
    int nt = (idx >> 5) & 3;
    int cm = idx >> 7;                          // c*2+m
    int c = cm >> 1, m = cm & 1;
    int n = nt*8 + (lane >> 2);
    int k = c*16 + (lane & 3)*4 + m*2;
    uint2 v;
    v.x = f2tf(g_bm[n*H + k]);
    v.y = f2tf(g_bm[n*H + k + 1]);
    g_bfrag[idx] = v;
}

// ---------------- kernel 2: T[b][r] = W2d x bm^T via mma.sync tf32 ----------------
// CTA 256 thr / 8 warps, 128 rows, K=512 in 32 chunks of 16.
// A: 6-stage cp.async pipeline (5-deep issue, 1 barrier/chunk).
// B: 64KB fragment blob. smem 112KB -> 2 CTA/SM.
#define SDW 132
#define WM_SMEM (65536 + 6*8192)    // 114688

__global__ void __launch_bounds__(256, 2) k_wgemm_mma(const float* __restrict__ Wg) {
    extern __shared__ char smem[];
    uint2* sbf = (uint2*)smem;                 // [8192] B frags
    char* sStg = smem + 65536;                 // 6 stages x 8KB
    float* sD = (float*)smem;                  // epilogue aliases blob

    int tid = threadIdx.x;
    int wid = tid >> 5, lane = tid & 31;
    int group = lane >> 2, tg = lane & 3;
    long r0 = (long)blockIdx.x * 128;
    int m0 = wid * 16;

    // group 0: B blob (contiguous 64KB)
    {
        const char* src = (const char*)g_bfrag;
        uint32_t sb0 = (uint32_t)__cvta_generic_to_shared(smem);
        #pragma unroll
        for (int p = 0; p < 16; p++) {
            int i = p*256 + tid;
            asm volatile("cp.async.cg.shared.global [%0], [%1], 16;"
                         :: "r"(sb0 + i*16), "l"(src + (long)i*16));
        }
        asm volatile("cp.async.commit_group;" ::: "memory");
    }

    auto issue = [&](int c, int stg) {
        uint32_t st = (uint32_t)__cvta_generic_to_shared(sStg) + stg*8192;
        #pragma unroll
        for (int q = 0; q < 2; q++) {
            int g = q*256 + tid;
            int row = g >> 2, i = g & 3;
            const float* src = Wg + (r0 + row)*H + c*16 + i*4;
            asm volatile("cp.async.cg.shared.global [%0], [%1], 16;"
                         :: "r"(st + row*64 + i*16), "l"(src));
        }
        asm volatile("cp.async.commit_group;" ::: "memory");
    };
    issue(0,0); issue(1,1); issue(2,2); issue(3,3); issue(4,4);

    float acc[4][4];
    #pragma unroll
    for (int i = 0; i < 4; i++)
        #pragma unroll
        for (int j = 0; j < 4; j++) acc[i][j] = 0.f;

    int rstg = 0, wstg = 5;
    for (int c = 0; c < 32; c++) {
        if (c < 28)       asm volatile("cp.async.wait_group 4;" ::: "memory");
        else if (c == 28) asm volatile("cp.async.wait_group 3;" ::: "memory");
        else if (c == 29) asm volatile("cp.async.wait_group 2;" ::: "memory");
        else if (c == 30) asm volatile("cp.async.wait_group 1;" ::: "memory");
        else              asm volatile("cp.async.wait_group 0;" ::: "memory");
        __syncthreads();
        if (c + 5 < 32) {
            issue(c + 5, wstg);
            if (++wstg == 6) wstg = 0;
        }

        const uint32_t* sA = (const uint32_t*)(sStg + rstg*8192);
        if (++rstg == 6) rstg = 0;
        uint4 a0v = *(const uint4*)(sA + (m0 + group)*16 + tg*4);
        uint4 a1v = *(const uint4*)(sA + (m0 + group + 8)*16 + tg*4);
        uint32_t ax0 = f2tf(__uint_as_float(a0v.x)), ax1 = f2tf(__uint_as_float(a1v.x));
        uint32_t ay0 = f2tf(__uint_as_float(a0v.y)), ay1 = f2tf(__uint_as_float(a1v.y));
        uint32_t az0 = f2tf(__uint_as_float(a0v.z)), az1 = f2tf(__uint_as_float(a1v.z));
        uint32_t aw0 = f2tf(__uint_as_float(a0v.w)), aw1 = f2tf(__uint_as_float(a1v.w));

        const uint2* bb = sbf + c*8*32 + lane;
        #pragma unroll
        for (int nt = 0; nt < 4; nt++) {
            uint2 b0 = bb[nt*32];           // m=0
            uint2 b1 = bb[(4 + nt)*32];     // m=1
            mma_tf32(acc[nt], ax0, ax1, ay0, ay1, b0.x, b0.y);
            mma_tf32(acc[nt], az0, az1, aw0, aw1, b1.x, b1.y);
        }
    }

    __syncthreads();   // all warps done reading blob before aliasing as sD
    #pragma unroll
    for (int nt = 0; nt < 4; nt++) {
        int n0 = nt*8 + tg*2;
        int rl = m0 + group;
        sD[(n0  )*SDW + rl    ] = acc[nt][0];
        sD[(n0+1)*SDW + rl    ] = acc[nt][1];
        sD[(n0  )*SDW + rl + 8] = acc[nt][2];
        sD[(n0+1)*SDW + rl + 8] = acc[nt][3];
    }
    __syncthreads();
    #pragma unroll
    for (int p = 0; p < 16; p++) {
        int i = p*256 + tid;
        int n = i >> 7, rl = i & 127;
        uint32_t t = f2tf(sD[n*SDW + rl]);     // pre-round for gemm2 B
        g_T[(long)n*NROW + r0 + rl] = __uint_as_float(t);
    }
}

// ---------------- kernel 3: fused = feat_a @ T^T (+bias +feat_a) via mma ----------
// tile 64x128, 8 warps, 4-stage cp.async (3-deep), 1 barrier/chunk, correct tail.
#define G2_STG   12288
#define G2_SMEM  (4*G2_STG)

__global__ void __launch_bounds__(256) k_gemm2(const float* __restrict__ Araw,
                                               const float* __restrict__ bias,
                                               float* __restrict__ out) {
    extern __shared__ char smem[];
    int b = blockIdx.z, kt = blockIdx.y, mt = blockIdx.x;
    int tid = threadIdx.x;
    int wid = tid >> 5, lane = tid & 31;
    int group = lane >> 2, tg = lane & 3;
    int wm = wid & 3, wc = wid >> 2;
    int row0 = mt * 64;
    const float* Ab = Araw + (long)b*LA*H;
    const float* Bb = g_T + (long)b*NROW + (long)kt*128*H;

    auto issue = [&](int c) {
        char* st = smem + (c & 3)*G2_STG;
        {
            int row = tid >> 2, i = tid & 3;
            const float* src = Ab + (long)(row0 + row)*H + c*16 + i*4;
            unsigned dst = (unsigned)__cvta_generic_to_shared(st + row*64 + i*16);
            int vsz = (row0 + row < LA) ? 16 : 0;
            asm volatile("cp.async.cg.shared.global [%0], [%1], 16, %2;"
                         :: "r"(dst), "l"(src), "r"(vsz));
        }
        #pragma unroll
        for (int q = 0; q < 2; q++) {
            int g2 = q*256 + tid;
            int row = g2 >> 2, i = g2 & 3;
            const float* src = Bb + (long)row*H + c*16 + i*4;
            unsigned dst = (unsigned)__cvta_generic_to_shared(st + 4096 + row*64 + i*16);
            asm volatile("cp.async.cg.shared.global [%0], [%1], 16;"
                         :: "r"(dst), "l"(src));
        }
        asm volatile("cp.async.commit_group;" ::: "memory");
    };

    issue(0); issue(1); issue(2);

    float acc[8][4];
    #pragma unroll
    for (int i = 0; i < 8; i++)
        #pragma unroll
        for (int j = 0; j < 4; j++) acc[i][j] = 0.f;

    for (int c = 0; c < 32; c++) {
        if (c < 30)       asm volatile("cp.async.wait_group 2;" ::: "memory");
        else if (c == 30) asm volatile("cp.async.wait_group 1;" ::: "memory");
        else              asm volatile("cp.async.wait_group 0;" ::: "memory");
        __syncthreads();
        if (c + 3 < 32) issue(c + 3);

        const char* st = smem + (c & 3)*G2_STG;
        const uint32_t* sA = (const uint32_t*)st;
        const uint32_t* sBt = (const uint32_t*)(st + 4096);

        uint4 a0v = *(const uint4*)(sA + (wm*16 + group)*16 + tg*4);
        uint4 a1v = *(const uint4*)(sA + (wm*16 + group + 8)*16 + tg*4);
        uint32_t ax0 = f2tf(__uint_as_float(a0v.x)), ax1 = f2tf(__uint_as_float(a1v.x));
        uint32_t ay0 = f2tf(__uint_as_float(a0v.y)), ay1 = f2tf(__uint_as_float(a1v.y));
        uint32_t az0 = f2tf(__uint_as_float(a0v.z)), az1 = f2tf(__uint_as_float(a1v.z));
        uint32_t aw0 = f2tf(__uint_as_float(a0v.w)), aw1 = f2tf(__uint_as_float(a1v.w));
        #pragma unroll
        for (int nt = 0; nt < 8; nt++) {
            uint4 bv = *(const uint4*)(sBt + (wc*64 + nt*8 + group)*16 + tg*4);
            mma_tf32(acc[nt], ax0, ax1, ay0, ay1, bv.x, bv.y);
            mma_tf32(acc[nt], az0, az1, aw0, aw1, bv.z, bv.w);
        }
    }

    int grow = row0 + wm*16 + group;
    #pragma unroll
    for (int nt = 0; nt < 8; nt++) {
        int col = kt*128 + wc*64 + nt*8 + tg*2;
        float2 bb = *(const float2*)(bias + col);
        #pragma unroll
        for (int h = 0; h < 2; h++) {
            int r = grow + h*8;
            if (r < LA) {
                float2 fa = *(const float2*)(Ab + (long)r*H + col);
                float2 o;
                o.x = acc[nt][h*2+0] + bb.x + fa.x;
                o.y = acc[nt][h*2+1] + bb.y + fa.y;
                *(float2*)(out + ((long)b*LA + r)*H + col) = o;
            }
        }
    }
}

// ---------------- kernel 4: LayerNorm, warp-per-row ----------------
__global__ void k_ln(const float* __restrict__ gamma, const float* __restrict__ beta,
                     float* __restrict__ out) {
    int wid = threadIdx.x >> 5, lane = threadIdx.x & 31;
    long row = (long)blockIdx.x*8 + wid;
    float4* xr = reinterpret_cast<float4*>(out + row*H);
    const float4* g4 = reinterpret_cast<const float4*>(gamma);
    const float4* b4 = reinterpret_cast<const float4*>(beta);

    float4 v[4];
    float s = 0.f, sq = 0.f;
    #pragma unroll
    for (int i = 0; i < 4; i++) {
        v[i] = xr[lane + i*32];
        s  += v[i].x + v[i].y + v[i].z + v[i].w;
        sq += v[i].x*v[i].x + v[i].y*v[i].y + v[i].z*v[i].z + v[i].w*v[i].w;
    }
    #pragma unroll
    for (int o = 16; o > 0; o >>= 1) {
        s  += __shfl_xor_sync(0xffffffffu, s,  o);
        sq += __shfl_xor_sync(0xffffffffu, sq, o);
    }
    float mu = s * (1.0f/H);
    float var = sq * (1.0f/H) - mu*mu;
    float rstd = rsqrtf(var + 1e-5f);
    #pragma unroll
    for (int i = 0; i < 4; i++) {
        float4 gg = __ldg(g4 + lane + i*32);
        float4 be = __ldg(b4 + lane + i*32);
        float4 o;
        o.x = (v[i].x - mu)*rstd*gg.x + be.x;
        o.y = (v[i].y - mu)*rstd*gg.y + be.y;
        o.z = (v[i].z - mu)*rstd*gg.z + be.z;
        o.w = (v[i].w - mu)*rstd*gg.w + be.w;
        xr[lane + i*32] = o;
    }
}

// ---------------- launch ----------------
extern "C" void kernel_launch(void* const* d_in, const int* in_sizes, int n_in,
                              void* d_out, int out_size) {
    const float* feat_a = (const float*)d_in[0];
    const float* feat_b = (const float*)d_in[1];
    const float* W      = (const float*)d_in[2];
    const float* bias   = (const float*)d_in[3];
    const float* gamma  = (const float*)d_in[4];
    const float* beta   = (const float*)d_in[5];
    float* out = (float*)d_out;

    static bool attr_done = false;
    if (!attr_done) {
        cudaFuncSetAttribute(k_wgemm_mma, cudaFuncAttributeMaxDynamicSharedMemorySize, WM_SMEM);
        cudaFuncSetAttribute(k_gemm2, cudaFuncAttributeMaxDynamicSharedMemorySize, G2_SMEM);
        attr_done = true;
    }

    k_bmean_part<<<dim3(16,32), 128>>>(feat_b);
    k_bmean_red<<<32, 512>>>();
    k_bfrag<<<32, 256>>>();
    k_wgemm_mma<<<2048, 256, WM_SMEM>>>(W);
    k_gemm2<<<dim3(5,4,32), 256, G2_SMEM>>>(feat_a, bias, out);
    k_ln<<<1200, 256>>>(gamma, beta, out);
}